// round 13
// baseline (speedup 1.0000x reference)
#include <cuda_runtime.h>
#include <math.h>

// Problem constants
#define BB 512
#define TT 512
#define II 8
#define HH 256

// 16 batch tiles, each an 8-CTA cluster. 128 CTAs, 1/SM, single wave.
// All h exchange is direct SMEM->peer-SMEM (DSMEM); no global state at all.
#define NBT 16
#define NCT 8          // CTAs per cluster (portable max)
#define BT 32          // batch rows per tile
#define CT 32          // h columns per CTA (=> 96 gh cols: r,z,n)
#define NCTAS (NBT * NCT)
#define NTHREADS 256

#define WS_PITCH 65    // float4 per W_hh row (2-phase-min banks)
#define WIH_PITCH 10
#define HP 1040        // h tile row pitch bytes (260 words; rows 4 apart -> disjoint banks)

// SMEM layout (bytes) — identical in every CTA (DSMEM peer addressing)
#define OFF_WS   0
#define SZ_WS    (96 * WS_PITCH * 16)          // 99840
#define OFF_H0   (OFF_WS + SZ_WS)              // 99840
#define SZ_H     (BT * HP)                     // 33280
#define OFF_H1   (OFF_H0 + SZ_H)               // 133120
#define OFF_WLIN (OFF_H1 + SZ_H)               // 166400 (256 floats)
#define OFF_WIH  (OFF_WLIN + 1024)             // 167424 (96*WIH_PITCH floats)
#define OFF_XS   (OFF_WIH + 96 * WIH_PITCH * 4)// 171264 (32*8 floats)
#define OFF_BIH  (OFF_XS + BT * 8 * 4)         // 172288 (96 floats)
#define OFF_BHH  (OFF_BIH + 96 * 4)            // 172672 (96 floats)
#define SMEM_TOTAL (OFF_BHH + 96 * 4)          // 173056

__device__ __forceinline__ unsigned smem_u32(const void* p) {
    unsigned a;
    asm("{ .reg .u64 t; cvta.to.shared.u64 t, %1; cvt.u32.u64 %0, t; }"
        : "=r"(a) : "l"(p));
    return a;
}

__device__ __forceinline__ unsigned mapa_u32(unsigned addr, unsigned rank) {
    unsigned r;
    asm("mapa.shared::cluster.u32 %0, %1, %2;" : "=r"(r) : "r"(addr), "r"(rank));
    return r;
}

__device__ __forceinline__ void st_dsmem(unsigned addr, float v) {
    asm volatile("st.shared::cluster.u32 [%0], %1;"
                 :: "r"(addr), "r"(__float_as_uint(v)) : "memory");
}

#define CLUSTER_SYNC()                                                  \
  do {                                                                  \
    asm volatile("barrier.cluster.arrive.aligned;" ::: "memory");       \
    asm volatile("barrier.cluster.wait.aligned;"   ::: "memory");       \
  } while (0)

__device__ __forceinline__ float sigmoidf_fast(float v) {
    return 1.0f / (1.0f + __expf(-v));
}

__device__ __forceinline__ float tanh_fast(float v) {
    v = fminf(fmaxf(v, -15.0f), 15.0f);
    float e = __expf(-2.0f * v);
    return __fdividef(1.0f - e, 1.0f + e);
}

__device__ __forceinline__ void ffma2(unsigned long long& d,
                                      unsigned long long a,
                                      unsigned long long b) {
    asm("fma.rn.f32x2 %0, %1, %2, %0;" : "+l"(d) : "l"(a), "l"(b));
}

__device__ __forceinline__ float f2sum(unsigned long long v) {
    return __uint_as_float((unsigned)v) + __uint_as_float((unsigned)(v >> 32));
}

__global__ void __launch_bounds__(NTHREADS, 1) __cluster_dims__(NCT, 1, 1)
gru_dsmem_kernel(const float* __restrict__ x,
                 const float* __restrict__ W_ih,
                 const float* __restrict__ W_hh,
                 const float* __restrict__ b_ih,
                 const float* __restrict__ b_hh,
                 const float* __restrict__ W_lin,
                 const float* __restrict__ b_lin,
                 float* __restrict__ out)
{
    extern __shared__ char sm[];
    float4* ws4  = (float4*)(sm + OFF_WS);      // [96][WS_PITCH]
    float*  wlin = (float*)(sm + OFF_WLIN);     // [256]
    float*  wih  = (float*)(sm + OFF_WIH);      // [96][WIH_PITCH]
    float*  xs   = (float*)(sm + OFF_XS);       // [32][8]
    float*  bihs = (float*)(sm + OFF_BIH);      // [96]
    float*  bhhs = (float*)(sm + OFF_BHH);      // [96]

    const int tid = threadIdx.x;
    const int cta = blockIdx.x;
    const int bt  = cta >> 3;                    // 0..15
    const int ct  = cta & 7;                     // 0..7 = cluster rank
    const int b0  = bt * BT;
    const int j0  = ct * CT;
    const float blin = __ldg(&b_lin[0]);

    const unsigned hb0_u32 = smem_u32(sm + OFF_H0);
    const unsigned hb1_u32 = smem_u32(sm + OFF_H1);

    // ---- one-time: weight slices into SMEM; zero h buffer 0 (h0 = 0) ----
    {
        const float4* whh4 = (const float4*)W_hh;
        for (int idx = tid; idx < 96 * 64; idx += NTHREADS) {
            int c = idx >> 6, k4 = idx & 63;
            int g = c >> 5, l = c & 31;
            int grow = g * HH + j0 + l;
            ws4[c * WS_PITCH + k4] = whh4[grow * (HH / 4) + k4];
        }
        for (int idx = tid; idx < 96 * WIH_PITCH; idx += NTHREADS) {
            int c = idx / WIH_PITCH, k = idx % WIH_PITCH;
            int g = c / 32, l = c % 32;
            int grow = g * HH + j0 + l;
            wih[idx] = (k < II) ? W_ih[grow * II + k] : 0.0f;
        }
        if (tid < 96) {
            int g = tid / 32, l = tid % 32;
            int grow = g * HH + j0 + l;
            bihs[tid] = b_ih[grow];
            bhhs[tid] = b_hh[grow];
        }
        for (int idx = tid; idx < 256; idx += NTHREADS) wlin[idx] = W_lin[idx];
        float* h0 = (float*)(sm + OFF_H0);
        for (int idx = tid; idx < SZ_H / 4; idx += NTHREADS) h0[idx] = 0.0f;
    }
    __syncthreads();
    CLUSTER_SYNC();   // SMEM (incl. zeroed buf0) live cluster-wide before DSMEM use

    // Warp layout: 8 warps = (2 col-halves) x (4 row-groups); lane: tx 0..15
    // (one col-triple), ty 0..1 (4 rows each). Warp covers 16 gh-cols ->
    // W-LDS traffic stays at the 8x49KB/SM budget.
    const int wid = tid >> 5, lane = tid & 31;
    const int half = wid & 1, rowGroup = wid >> 1;
    const int tx = lane & 15, ty = lane >> 4;
    const int rowBase = rowGroup * 8 + ty * 4;
    const int cH = half * 16 + tx;               // 0..31 local gh-col

    const ulonglong2* w0q = (const ulonglong2*)(ws4 + (0 * 32 + cH) * WS_PITCH);
    const ulonglong2* w1q = (const ulonglong2*)(ws4 + (1 * 32 + cH) * WS_PITCH);
    const ulonglong2* w2q = (const ulonglong2*)(ws4 + (2 * 32 + cH) * WS_PITCH);
    const unsigned long long* wxr = (const unsigned long long*)&wih[(0 * 32 + cH) * WIH_PITCH];
    const unsigned long long* wxz = (const unsigned long long*)&wih[(1 * 32 + cH) * WIH_PITCH];
    const unsigned long long* wxn = (const unsigned long long*)&wih[(2 * 32 + cH) * WIH_PITCH];
    const float bir = bihs[cH], biz = bihs[32 + cH], bin = bihs[64 + cH];
    const float bhr = bhhs[cH], bhz = bhhs[32 + cH], bhn = bhhs[64 + cH];

    // This thread's destination byte offset inside any peer's h buffer
    const unsigned off0 = (unsigned)(rowBase * HP + (j0 + cH) * 4);

    float hreg[4] = {0.f, 0.f, 0.f, 0.f};

    for (int t = 0; t < TT; t++) {
        const int p = t & 1;
        const char* hb = sm + (p ? OFF_H1 : OFF_H0);          // h_t (local)
        const unsigned dst_base = p ? hb0_u32 : hb1_u32;      // h_{t+1} target

        // stage x_t [32][8] (consumed after the syncthreads below)
        if (tid < BT * 2) {
            int r = tid >> 1, hf = tid & 1;
            const float4* xsrc = (const float4*)&x[((size_t)(b0 + r) * TT + t) * II];
            ((float4*)xs)[r * 2 + hf] = __ldg(&xsrc[hf]);
        }

        // ---- GEMM from LOCAL smem: acc[g][i] = sum_k h[rowBase+i][k]*W[g][cH][k]
        unsigned long long acc[3][4];
        #pragma unroll
        for (int g = 0; g < 3; g++)
            #pragma unroll
            for (int i = 0; i < 4; i++) acc[g][i] = 0ull;

        const char* hr0 = hb + (rowBase + 0) * HP;
        const char* hr1 = hb + (rowBase + 1) * HP;
        const char* hr2 = hb + (rowBase + 2) * HP;
        const char* hr3 = hb + (rowBase + 3) * HP;

        #pragma unroll 4
        for (int k4 = 0; k4 < 64; k4++) {
            ulonglong2 w0 = w0q[k4], w1 = w1q[k4], w2 = w2q[k4];
            ulonglong2 h0 = *(const ulonglong2*)(hr0 + k4 * 16);
            ulonglong2 h1 = *(const ulonglong2*)(hr1 + k4 * 16);
            ulonglong2 h2 = *(const ulonglong2*)(hr2 + k4 * 16);
            ulonglong2 h3 = *(const ulonglong2*)(hr3 + k4 * 16);
            ffma2(acc[0][0], h0.x, w0.x); ffma2(acc[0][0], h0.y, w0.y);
            ffma2(acc[1][0], h0.x, w1.x); ffma2(acc[1][0], h0.y, w1.y);
            ffma2(acc[2][0], h0.x, w2.x); ffma2(acc[2][0], h0.y, w2.y);
            ffma2(acc[0][1], h1.x, w0.x); ffma2(acc[0][1], h1.y, w0.y);
            ffma2(acc[1][1], h1.x, w1.x); ffma2(acc[1][1], h1.y, w1.y);
            ffma2(acc[2][1], h1.x, w2.x); ffma2(acc[2][1], h1.y, w2.y);
            ffma2(acc[0][2], h2.x, w0.x); ffma2(acc[0][2], h2.y, w0.y);
            ffma2(acc[1][2], h2.x, w1.x); ffma2(acc[1][2], h2.y, w1.y);
            ffma2(acc[2][2], h2.x, w2.x); ffma2(acc[2][2], h2.y, w2.y);
            ffma2(acc[0][3], h3.x, w0.x); ffma2(acc[0][3], h3.y, w0.y);
            ffma2(acc[1][3], h3.x, w1.x); ffma2(acc[1][3], h3.y, w1.y);
            ffma2(acc[2][3], h3.x, w2.x); ffma2(acc[2][3], h3.y, w2.y);
        }

        __syncthreads();   // xs ready for gates

        // ---- pred[t-1] on ct7 from the local full h_t tile ----
        if (ct == NCT - 1 && t > 0) {
            const int row = tid >> 3;            // 0..31
            const int oct = tid & 7;             // 32 cols each
            const ulonglong2* hrq = (const ulonglong2*)(hb + row * HP + oct * 128);
            const ulonglong2* wlq = (const ulonglong2*)wlin + oct * 8;
            unsigned long long a = 0ull;
            #pragma unroll
            for (int q = 0; q < 8; q++) {
                ulonglong2 hv = hrq[q], wv = wlq[q];
                ffma2(a, hv.x, wv.x);
                ffma2(a, hv.y, wv.y);
            }
            float v = f2sum(a);
            v += __shfl_xor_sync(0xffffffffu, v, 1);
            v += __shfl_xor_sync(0xffffffffu, v, 2);
            v += __shfl_xor_sync(0xffffffffu, v, 4);
            if (oct == 0)
                out[(size_t)(b0 + row) * TT + (t - 1)] = v + blin;
        }

        // ---- fused gates -> h_{t+1} (4 values per thread) ----
        float hn[4];
        #pragma unroll
        for (int i = 0; i < 4; i++) {
            const int r = rowBase + i;
            const unsigned long long* xq = (const unsigned long long*)&xs[r * II];
            unsigned long long ar = 0ull, az = 0ull, an = 0ull;
            #pragma unroll
            for (int kq = 0; kq < 4; kq++) {
                unsigned long long xv = xq[kq];
                ffma2(ar, xv, wxr[kq]);
                ffma2(az, xv, wxz[kq]);
                ffma2(an, xv, wxn[kq]);
            }
            float rr = sigmoidf_fast(bir + f2sum(ar) + f2sum(acc[0][i]) + bhr);
            float zz = sigmoidf_fast(biz + f2sum(az) + f2sum(acc[1][i]) + bhz);
            float nn = tanh_fast(bin + f2sum(an) + rr * (f2sum(acc[2][i]) + bhn));
            hn[i] = (1.0f - zz) * nn + zz * hreg[i];
            hreg[i] = hn[i];
        }

        // ---- broadcast: write 4 values straight into all 8 CTAs' SMEM ----
        #pragma unroll
        for (int rk = 0; rk < NCT; rk++) {
            unsigned base = mapa_u32(dst_base, (unsigned)rk) + off0;
            st_dsmem(base,          hn[0]);
            st_dsmem(base + HP,     hn[1]);
            st_dsmem(base + 2 * HP, hn[2]);
            st_dsmem(base + 3 * HP, hn[3]);
        }

        // one cluster barrier per step: release our stores, acquire peers'
        CLUSTER_SYNC();
    }

    // ---- epilogue: h_T landed in buf0 (T even); ct7 emits pred[T-1] ----
    if (ct == NCT - 1) {
        const char* hb = sm + OFF_H0;
        const int row = tid >> 3;
        const int oct = tid & 7;
        const ulonglong2* hrq = (const ulonglong2*)(hb + row * HP + oct * 128);
        const ulonglong2* wlq = (const ulonglong2*)wlin + oct * 8;
        unsigned long long a = 0ull;
        #pragma unroll
        for (int q = 0; q < 8; q++) {
            ulonglong2 hv = hrq[q], wv = wlq[q];
            ffma2(a, hv.x, wv.x);
            ffma2(a, hv.y, wv.y);
        }
        float v = f2sum(a);
        v += __shfl_xor_sync(0xffffffffu, v, 1);
        v += __shfl_xor_sync(0xffffffffu, v, 2);
        v += __shfl_xor_sync(0xffffffffu, v, 4);
        if (oct == 0)
            out[(size_t)(b0 + row) * TT + (TT - 1)] = v + blin;
    }
}

extern "C" void kernel_launch(void* const* d_in, const int* in_sizes, int n_in,
                              void* d_out, int out_size) {
    const float* x     = (const float*)d_in[0];
    const float* W_ih  = (const float*)d_in[1];
    const float* W_hh  = (const float*)d_in[2];
    const float* b_ih  = (const float*)d_in[3];
    const float* b_hh  = (const float*)d_in[4];
    const float* W_lin = (const float*)d_in[5];
    const float* b_lin = (const float*)d_in[6];
    float* out = (float*)d_out;

    cudaFuncSetAttribute(gru_dsmem_kernel,
                         cudaFuncAttributeMaxDynamicSharedMemorySize, SMEM_TOTAL);

    gru_dsmem_kernel<<<NCTAS, NTHREADS, SMEM_TOTAL>>>(
        x, W_ih, W_hh, b_ih, b_hh, W_lin, b_lin, out);
}

// round 15
// speedup vs baseline: 1.8600x; 1.8600x over previous
#include <cuda_runtime.h>
#include <math.h>

// Problem constants
#define BB 512
#define TT 512
#define II 8
#define HH 256

// 16 batch tiles x 8 col-CTAs = 128 CTAs, 1/SM, single wave.
#define NBT 16
#define NCT 8
#define BT 32          // batch rows per tile
#define CT 32          // h cols per CTA (=> 96 gh rows: r,z,n)
#define NCTAS (NBT * NCT)
#define NTHREADS 256   // 8 warps = 4 rowGroups x 2 colGroups

// SMEM pitches in float4
#define WS_PITCH 65
#define HS_PITCH 65
#define WIH_PITCH 10

// Persistent device state
__device__ float g_h[2][BB][HH];               // ping-pong h (buf (t+1)&1 = h_{t+1})
__device__ unsigned g_flag[NBT][NCT][32];      // per-CTA step flags (own 128B lines)
__device__ unsigned g_bar_count = 0;
__device__ unsigned g_bar_gen = 0;

__device__ __forceinline__ void grid_barrier() {   // end-of-kernel only
    __syncthreads();
    if (threadIdx.x == 0) {
        __threadfence();
        volatile unsigned* vgen = (volatile unsigned*)&g_bar_gen;
        unsigned gen = *vgen;
        unsigned arrived = atomicAdd(&g_bar_count, 1u);
        if (arrived == NCTAS - 1u) {
            *((volatile unsigned*)&g_bar_count) = 0u;
            __threadfence();
            *vgen = gen + 1u;
        } else {
            while (*vgen == gen) { }
        }
        __threadfence();
    }
    __syncthreads();
}

__device__ __forceinline__ unsigned ld_acq_gpu(const unsigned* p) {
    unsigned v;
    asm volatile("ld.acquire.gpu.u32 %0, [%1];" : "=r"(v) : "l"(p) : "memory");
    return v;
}

__device__ __forceinline__ void st_rel_gpu(unsigned* p, unsigned v) {
    asm volatile("st.release.gpu.u32 [%0], %1;" :: "l"(p), "r"(v) : "memory");
}

__device__ __forceinline__ float sigmoidf_fast(float v) {
    return 1.0f / (1.0f + __expf(-v));
}

__device__ __forceinline__ float tanh_fast(float v) {
    v = fminf(fmaxf(v, -15.0f), 15.0f);
    float e = __expf(-2.0f * v);
    return __fdividef(1.0f - e, 1.0f + e);
}

// Blackwell packed dual-fp32 FMA
__device__ __forceinline__ void ffma2(unsigned long long& d,
                                      unsigned long long a,
                                      unsigned long long b) {
    asm("fma.rn.f32x2 %0, %1, %2, %0;" : "+l"(d) : "l"(a), "l"(b));
}

__device__ __forceinline__ float f2sum(unsigned long long v) {
    return __uint_as_float((unsigned)v) + __uint_as_float((unsigned)(v >> 32));
}

__device__ __forceinline__ void cp16(unsigned dst, const void* src) {
    asm volatile("cp.async.cg.shared.global [%0], [%1], 16;"
                 :: "r"(dst), "l"(src) : "memory");
}

// All lanes acquire-poll both producers of chunk c (flags >= t).
#define POLL(c)                                                               \
  do {                                                                        \
    const unsigned* f0_ = &g_flag[bt][2 * (c)][0];                            \
    const unsigned* f1_ = &g_flag[bt][2 * (c) + 1][0];                        \
    while (ld_acq_gpu(f0_) < (unsigned)t) { }                                 \
    while (ld_acq_gpu(f1_) < (unsigned)t) { }                                 \
  } while (0)

// Warp issues cp.async for ITS 8 rows of h-chunk c (8 rows x 16 f4 = 2KB/warp)
#define ISSUE(c)                                                              \
  do {                                                                        \
    int row_ = rowGroup * 8 + (lane >> 2);                                    \
    int kb_ = (c) * 16 + (lane & 3) * 4;                                      \
    const float4* src_ = ((const float4*)&g_h[p][b0 + row_][0]) + kb_;        \
    unsigned dst_ = (unsigned)__cvta_generic_to_shared(                       \
                        &hs4[row_ * HS_PITCH + kb_]);                         \
    cp16(dst_,      src_);                                                    \
    cp16(dst_ + 16, src_ + 1);                                                \
    cp16(dst_ + 32, src_ + 2);                                                \
    cp16(dst_ + 48, src_ + 3);                                                \
    asm volatile("cp.async.commit_group;" ::: "memory");                      \
  } while (0)

// One 16-k4 GEMM chunk: wait own cp.async group, warp-sync, FFMA2.
#define CHUNK(CBASE, WAITN)                                                   \
  {                                                                           \
    asm volatile("cp.async.wait_group " #WAITN ";" ::: "memory");             \
    __syncwarp();                                                             \
    _Pragma("unroll 4")                                                       \
    for (int kk = 0; kk < 16; kk++) {                                         \
      const int k4 = (CBASE) + kk;                                            \
      ulonglong2 w0 = w0q[k4], w1 = w1q[k4], w2 = w2q[k4];                    \
      _Pragma("unroll")                                                       \
      for (int i = 0; i < 4; i++) {                                           \
        ulonglong2 hv = hq[i][k4];                                            \
        ffma2(acc0[i], hv.x, w0.x); ffma2(acc0[i], hv.y, w0.y);               \
        ffma2(acc1[i], hv.x, w1.x); ffma2(acc1[i], hv.y, w1.y);               \
        ffma2(acc2[i], hv.x, w2.x); ffma2(acc2[i], hv.y, w2.y);               \
      }                                                                       \
    }                                                                         \
  }

// Per-warp pred over OWN 8 rows (colGroup 0 warps of the pred CTA).
// Lane: prow = rowGroup*8 + (lane>>2), q = lane&3 covers 16 ulonglong2.
#define PRED_OWN_ROWS(TIDX)                                                   \
  do {                                                                        \
    int prow_ = rowGroup * 8 + (lane >> 2);                                   \
    int q_ = lane & 3;                                                        \
    const ulonglong2* hr_ = (const ulonglong2*)(hs4 + prow_ * HS_PITCH);      \
    const ulonglong2* wl_ = (const ulonglong2*)wlin;                          \
    unsigned long long a_ = 0ull;                                             \
    _Pragma("unroll")                                                         \
    for (int j = 0; j < 16; j++) {                                            \
      ulonglong2 hv = hr_[q_ * 16 + j];                                       \
      ulonglong2 wv = wl_[q_ * 16 + j];                                       \
      ffma2(a_, hv.x, wv.x);                                                  \
      ffma2(a_, hv.y, wv.y);                                                  \
    }                                                                         \
    float v_ = f2sum(a_);                                                     \
    v_ += __shfl_xor_sync(0xffffffffu, v_, 1);                                \
    v_ += __shfl_xor_sync(0xffffffffu, v_, 2);                                \
    if (q_ == 0)                                                              \
      out[(size_t)(b0 + prow_) * TT + (TIDX)] = v_ + blin;                    \
  } while (0)

__global__ void __launch_bounds__(NTHREADS, 1)
gru_persistent_kernel(const float* __restrict__ x,
                      const float* __restrict__ W_ih,
                      const float* __restrict__ W_hh,
                      const float* __restrict__ b_ih,
                      const float* __restrict__ b_hh,
                      const float* __restrict__ W_lin,
                      const float* __restrict__ b_lin,
                      float* __restrict__ out)
{
    extern __shared__ char smem_raw[];
    float4* ws4 = (float4*)smem_raw;                 // [96][WS_PITCH] W_hh slice
    float4* hs4 = ws4 + 96 * WS_PITCH;               // [32][HS_PITCH] h tile
    float*  wlin = (float*)(hs4 + 32 * HS_PITCH);    // [256] (16B aligned)
    float*  wih  = wlin + 256;                       // [96][WIH_PITCH]
    float*  xs   = wih + 96 * WIH_PITCH;             // [32][8]
    float*  bihs = xs + 32 * 8;                      // [96]
    float*  bhhs = bihs + 96;                        // [96]

    const int tid = threadIdx.x;
    const int cta = blockIdx.x;
    const int bt  = cta >> 3;                        // 0..15
    const int ct  = cta & 7;                         // 0..7
    const int b0  = bt * BT;
    const int j0  = ct * CT;
    const float blin = __ldg(&b_lin[0]);

    // ---- one-time: weight slices into SMEM ----
    {
        const float4* whh4 = (const float4*)W_hh;
        for (int idx = tid; idx < 96 * 64; idx += NTHREADS) {
            int c = idx >> 6, k4 = idx & 63;
            int g = c >> 5, l = c & 31;
            int grow = g * HH + j0 + l;
            ws4[c * WS_PITCH + k4] = whh4[grow * (HH / 4) + k4];
        }
        for (int idx = tid; idx < 96 * WIH_PITCH; idx += NTHREADS) {
            int c = idx / WIH_PITCH, k = idx % WIH_PITCH;
            int g = c / 32, l = c % 32;
            int grow = g * HH + j0 + l;
            wih[idx] = (k < II) ? W_ih[grow * II + k] : 0.0f;
        }
        if (tid < 96) {
            int g = tid / 32, l = tid % 32;
            int grow = g * HH + j0 + l;
            bihs[tid] = b_ih[grow];
            bhhs[tid] = b_hh[grow];
        }
        for (int idx = tid; idx < 256; idx += NTHREADS) wlin[idx] = W_lin[idx];
    }
    __syncthreads();   // weights visible CTA-wide (no grid barrier needed: t=0
                       // is special-cased, g_h buf written before first read)

    // Warp decomposition: 8 warps = 4 rowGroups x 2 colGroups.
    const int wid = tid >> 5, lane = tid & 31;
    const int colGroup = wid & 1, rowGroup = wid >> 1;
    const int tx = lane & 15, ty = lane >> 4;
    const int localCol = colGroup * 16 + tx;         // 0..31
    const int r0 = rowGroup * 8 + ty * 4;            // this thread's 4 rows

    const ulonglong2* w0q = (const ulonglong2*)(ws4 + localCol * WS_PITCH);
    const ulonglong2* w1q = (const ulonglong2*)(ws4 + (32 + localCol) * WS_PITCH);
    const ulonglong2* w2q = (const ulonglong2*)(ws4 + (64 + localCol) * WS_PITCH);
    const ulonglong2* hq[4];
    #pragma unroll
    for (int i = 0; i < 4; i++)
        hq[i] = (const ulonglong2*)(hs4 + (r0 + i) * HS_PITCH);

    const unsigned long long* wxr = (const unsigned long long*)&wih[localCol * WIH_PITCH];
    const unsigned long long* wxz = (const unsigned long long*)&wih[(32 + localCol) * WIH_PITCH];
    const unsigned long long* wxn = (const unsigned long long*)&wih[(64 + localCol) * WIH_PITCH];
    const float bir = bihs[localCol], biz = bihs[32 + localCol], bin = bihs[64 + localCol];
    const float bhr = bhhs[localCol], bhz = bhhs[32 + localCol], bhn = bhhs[64 + localCol];

    float hreg[4] = {0.f, 0.f, 0.f, 0.f};           // own h (4 rows x 1 col)

    for (int t = 0; t < TT; t++) {
        const int p = t & 1;                         // read buf (h_t); skip at t=0
        const int nb = (t + 1) & 1;                  // write buf (h_{t+1})

        // x_t for this warp's rows (duplicate writes across colGroup pair: same data)
        if (lane < 16) {
            int r = rowGroup * 8 + (lane >> 1), hf = lane & 1;
            const float4* xsrc = (const float4*)&x[((size_t)(b0 + r) * TT + t) * II];
            ((float4*)xs)[r * 2 + hf] = __ldg(&xsrc[hf]);
        }
        __syncwarp();

        unsigned long long acc0[4], acc1[4], acc2[4];
        #pragma unroll
        for (int i = 0; i < 4; i++) { acc0[i] = 0ull; acc1[i] = 0ull; acc2[i] = 0ull; }

        if (t > 0) {
            // Interleaved per-chunk: poll 2 producers -> own cp.async -> GEMM
            POLL(0); ISSUE(0);
            POLL(1); ISSUE(1);
            CHUNK(0, 1)
            POLL(2); ISSUE(2);
            CHUNK(16, 1)
            POLL(3); ISSUE(3);
            CHUNK(32, 1)
            CHUNK(48, 0)

            // pred[t-1] from own rows of h_t (pred CTA, colGroup 0 warps only)
            if (ct == NCT - 1 && colGroup == 0) PRED_OWN_ROWS(t - 1);
        }
        // (t == 0: h_0 = 0 -> acc stays 0, no loads, no polls)

        // ---- fused gates + h update ----
        #pragma unroll
        for (int i = 0; i < 4; i++) {
            const int r = r0 + i;
            const unsigned long long* xq = (const unsigned long long*)&xs[r * II];
            unsigned long long ar = 0ull, az = 0ull, an = 0ull;
            #pragma unroll
            for (int kq = 0; kq < 4; kq++) {
                unsigned long long xv = xq[kq];
                ffma2(ar, xv, wxr[kq]);
                ffma2(az, xv, wxz[kq]);
                ffma2(an, xv, wxn[kq]);
            }
            float rr = sigmoidf_fast(bir + f2sum(ar) + f2sum(acc0[i]) + bhr);
            float zz = sigmoidf_fast(biz + f2sum(az) + f2sum(acc1[i]) + bhz);
            float nn = tanh_fast(bin + f2sum(an) + rr * (f2sum(acc2[i]) + bhn));
            float hn = (1.0f - zz) * nn + zz * hreg[i];
            hreg[i] = hn;
            __stcg(&g_h[nb][b0 + r][j0 + localCol], hn);
        }

        // ---- publish: ONE CTA barrier per step, then release flag ----
        __syncthreads();
        if (tid == 0) st_rel_gpu(&g_flag[bt][ct][0], (unsigned)(t + 1));
    }

    // ---- epilogue: pred[TT-1] on the pred CTA from h_TT (buf 0) ----
    if (ct == NCT - 1) {
        {
            const unsigned* f = &g_flag[bt][lane & 7][0];
            while (ld_acq_gpu(f) < (unsigned)TT) { }
        }
        __syncwarp();
        // load own rows, all 4 chunks
        {
            int row_ = rowGroup * 8 + (lane >> 2);
            int kb_ = (lane & 3) * 4;
            const float4* src_ = ((const float4*)&g_h[0][b0 + row_][0]);
            unsigned dst_ = (unsigned)__cvta_generic_to_shared(
                                &hs4[row_ * HS_PITCH]);
            #pragma unroll
            for (int c = 0; c < 4; c++) {
                int k4 = c * 16 + kb_;
                #pragma unroll
                for (int j = 0; j < 4; j++)
                    cp16(dst_ + (k4 + j) * 16, src_ + k4 + j);
            }
            asm volatile("cp.async.commit_group;" ::: "memory");
            asm volatile("cp.async.wait_group 0;" ::: "memory");
            __syncwarp();
        }
        if (colGroup == 0) PRED_OWN_ROWS(TT - 1);
    }

    // ---- all CTAs done, then reset own flag for the next graph replay ----
    grid_barrier();
    if (tid == 0) g_flag[bt][ct][0] = 0u;
}

extern "C" void kernel_launch(void* const* d_in, const int* in_sizes, int n_in,
                              void* d_out, int out_size) {
    const float* x     = (const float*)d_in[0];
    const float* W_ih  = (const float*)d_in[1];
    const float* W_hh  = (const float*)d_in[2];
    const float* b_ih  = (const float*)d_in[3];
    const float* b_hh  = (const float*)d_in[4];
    const float* W_lin = (const float*)d_in[5];
    const float* b_lin = (const float*)d_in[6];
    float* out = (float*)d_out;

    size_t smem = (size_t)(96 * WS_PITCH + 32 * HS_PITCH) * sizeof(float4)
                + (size_t)(256 + 96 * WIH_PITCH + 32 * 8 + 96 + 96) * sizeof(float);

    cudaFuncSetAttribute(gru_persistent_kernel,
                         cudaFuncAttributeMaxDynamicSharedMemorySize, (int)smem);

    gru_persistent_kernel<<<NCTAS, NTHREADS, smem>>>(
        x, W_ih, W_hh, b_ih, b_hh, W_lin, b_lin, out);
}